// round 8
// baseline (speedup 1.0000x reference)
#include <cuda_runtime.h>
#include <cstdint>

// LSTM B=128, T=2048, F=3, U=256. 16 clusters x 8 CTAs, CTA = 8 batch rows x 32 units (128 gate cols).
// R4: h exchange = each CTA stores unique h slice (1KB) in own SMEM; peers PULL via ld.shared::cluster
//     and duplicate locally into the FFMA2 {h,h} tile. Sync = barrier.cluster (HW, release/acquire).
//     No global atomics, no L2 spins, no st.async storms.

#define BB 128
#define TT 2048
#define FF 3
#define UU 256
#define G4 1024
#define NCTA 128
#define NTHR 256
#define CLUSTER 8

// SMEM layout (float offsets)
#define OFF_WH   0        // 256*128 = 32768   permuted Wh slice [k][u_l*4+gate]
#define OFF_HD   32768    // 8*516   = 4128    duplicated h tile [b][2k]={h,h}, stride 516
#define OFF_HX   36896    // 2*8*32  = 512     own h exchange slices, [buf][b][u_l]
#define OFF_BIAS 37408    // 128
#define OFF_WX   37536    // 384
#define OFF_XS   37920    // 64 (x tile, double-buffered by parity)
#define SMEM_FLOATS 37984
#define SMEM_BYTES (SMEM_FLOATS * 4)
#define HSTRIDE 516

__device__ __forceinline__ float sig_f(float x) {
    x = fminf(fmaxf(x, -30.f), 30.f);
    float e = __expf(-x);
    return __fdividef(1.f, 1.f + e);
}

__device__ __forceinline__ float tanh_f(float x) {
    float ax = fminf(fabsf(x), 15.f);
    float e = __expf(-2.f * ax);
    float r = __fdividef(1.f - e, 1.f + e);
    return copysignf(r, x);
}

__device__ __forceinline__ void ffma2(unsigned long long& acc,
                                      unsigned long long a,
                                      unsigned long long b) {
    asm("fma.rn.f32x2 %0, %1, %2, %0;" : "+l"(acc) : "l"(a), "l"(b));
}

__device__ __forceinline__ float4 ld_dsmem_v4(uint32_t addr) {
    float4 v;
    asm volatile("ld.shared::cluster.v4.f32 {%0, %1, %2, %3}, [%4];"
                 : "=f"(v.x), "=f"(v.y), "=f"(v.z), "=f"(v.w) : "r"(addr));
    return v;
}

__global__ void __launch_bounds__(NTHR, 1) __cluster_dims__(CLUSTER, 1, 1)
lstm_persistent_kernel(
    const float* __restrict__ x,     // [B, T, F]
    const float* __restrict__ Wx,    // [F, 4U]
    const float* __restrict__ Wh,    // [U, 4U]
    const float* __restrict__ bias,  // [4U]
    float* __restrict__ out,         // ys [B,T,U] (+ h_T, c_T if write_hc)
    int write_hc)
{
    extern __shared__ float sm[];
    float* whs = sm + OFF_WH;
    float* hd  = sm + OFF_HD;
    float* hx  = sm + OFF_HX;
    float* bs  = sm + OFF_BIAS;
    float* wxs = sm + OFF_WX;
    float* xs  = sm + OFF_XS;

    const int tid = threadIdx.x;
    const int RB  = blockIdx.x >> 3;   // cluster id 0..15
    const int CB  = blockIdx.x & 7;    // rank in cluster = gate-column block
    const int gb  = RB * 8;

    const uint32_t smem_u32 = (uint32_t)__cvta_generic_to_shared(sm);

    // per-rank DSMEM base addresses
    uint32_t r_base[CLUSTER];
    #pragma unroll
    for (int r = 0; r < CLUSTER; r++)
        asm("mapa.shared::cluster.u32 %0, %1, %2;"
            : "=r"(r_base[r]) : "r"(smem_u32), "r"(r));

    // ---------------- setup: permuted weights -> SMEM ----------------
    #pragma unroll
    for (int g = 0; g < 4; g++) {
        const int gbase = g * UU + CB * 32;
        for (int i = tid; i < 256 * 32; i += NTHR) {
            int k = i >> 5, ul = i & 31;
            whs[k * 128 + ul * 4 + g] = Wh[k * G4 + gbase + ul];
        }
        for (int i = tid; i < 3 * 32; i += NTHR) {
            int f = i >> 5, ul = i & 31;
            wxs[f * 128 + ul * 4 + g] = Wx[f * G4 + gbase + ul];
        }
    }
    if (tid < 128) {
        int ul = tid >> 2, g = tid & 3;
        bs[tid] = bias[g * UU + CB * 32 + ul];
    }
    // zero duplicated tile (step 0 reads h = 0)
    for (int i = tid; i < 8 * HSTRIDE; i += NTHR) hd[i] = 0.f;

    const int u_l = tid >> 3;   // 0..31
    const int b_l = tid & 7;    // 0..7
    const int gcol = CB * 32 + u_l;

    // pull mapping: thread t -> rank pr, batch pb, unit quarter pq (8 units)
    const int pr = tid >> 5;
    const int pb = (tid & 31) >> 2;
    const int pq = tid & 3;
    const uint32_t pull_base = r_base[pr] + (uint32_t)(OFF_HX + pb * 32 + pq * 8) * 4;
    float* dup_dst = hd + pb * HSTRIDE + 2 * (pr * 32 + pq * 8);

    float c = 0.f;
    float xpre = 0.f;
    if (tid < 24) xpre = __ldg(&x[(size_t)(gb + tid / 3) * (TT * FF) + tid % 3]);

    __syncthreads();
    asm volatile("barrier.cluster.arrive.aligned;" ::: "memory");
    asm volatile("barrier.cluster.wait.aligned;"   ::: "memory");

    for (int s = 0; s < TT; s++) {
        const int p = s & 1;
        if (tid < 24) xs[p * 32 + tid] = xpre;

        // -------- pull peers' h slices (buffer p) and duplicate into hd --------
        if (s > 0) {
            const uint32_t src = pull_base + (uint32_t)(p * 256) * 4;
            float4 v0 = ld_dsmem_v4(src);
            float4 v1 = ld_dsmem_v4(src + 16);
            *reinterpret_cast<float4*>(dup_dst + 0)  = make_float4(v0.x, v0.x, v0.y, v0.y);
            *reinterpret_cast<float4*>(dup_dst + 4)  = make_float4(v0.z, v0.z, v0.w, v0.w);
            *reinterpret_cast<float4*>(dup_dst + 8)  = make_float4(v1.x, v1.x, v1.y, v1.y);
            *reinterpret_cast<float4*>(dup_dst + 12) = make_float4(v1.z, v1.z, v1.w, v1.w);
        }
        __syncthreads();

        // -------- acc init: bias + x @ Wx --------
        float a0, a1, a2, a3;
        {
            float4 bb4 = *reinterpret_cast<const float4*>(bs + u_l * 4);
            a0 = bb4.x; a1 = bb4.y; a2 = bb4.z; a3 = bb4.w;
            float xv0 = xs[p * 32 + b_l * 3 + 0];
            float xv1 = xs[p * 32 + b_l * 3 + 1];
            float xv2 = xs[p * 32 + b_l * 3 + 2];
            float4 w;
            w = *reinterpret_cast<const float4*>(wxs + 0 * 128 + u_l * 4);
            a0 = fmaf(xv0, w.x, a0); a1 = fmaf(xv0, w.y, a1);
            a2 = fmaf(xv0, w.z, a2); a3 = fmaf(xv0, w.w, a3);
            w = *reinterpret_cast<const float4*>(wxs + 1 * 128 + u_l * 4);
            a0 = fmaf(xv1, w.x, a0); a1 = fmaf(xv1, w.y, a1);
            a2 = fmaf(xv1, w.z, a2); a3 = fmaf(xv1, w.w, a3);
            w = *reinterpret_cast<const float4*>(wxs + 2 * 128 + u_l * 4);
            a0 = fmaf(xv2, w.x, a0); a1 = fmaf(xv2, w.y, a1);
            a2 = fmaf(xv2, w.z, a2); a3 = fmaf(xv2, w.w, a3);
        }

        // prefetch next x
        if (tid < 24 && s + 1 < TT)
            xpre = __ldg(&x[(size_t)(gb + tid / 3) * (TT * FF) + (size_t)(s + 1) * FF + tid % 3]);

        // -------- GEMM: z += h @ Wh, packed f32x2, K=256 --------
        unsigned long long a01, a23;
        asm("mov.b64 %0, {%1, %2};" : "=l"(a01) : "f"(a0), "f"(a1));
        asm("mov.b64 %0, {%1, %2};" : "=l"(a23) : "f"(a2), "f"(a3));
        {
            const float* whp = whs + u_l * 4;
            const unsigned long long* hp =
                reinterpret_cast<const unsigned long long*>(hd + b_l * HSTRIDE);
            #pragma unroll 8
            for (int k = 0; k < UU; k++) {
                ulonglong2 wv = *reinterpret_cast<const ulonglong2*>(whp + k * 128);
                unsigned long long hv = hp[k];
                ffma2(a01, hv, wv.x);
                ffma2(a23, hv, wv.y);
            }
        }
        asm("mov.b64 {%0, %1}, %2;" : "=f"(a0), "=f"(a1) : "l"(a01));
        asm("mov.b64 {%0, %1}, %2;" : "=f"(a2), "=f"(a3) : "l"(a23));

        // -------- gates / state / outputs / own-slice store --------
        {
            float ig = sig_f(a0);
            float fg = sig_f(a1);
            float gg = tanh_f(a2);
            float og = sig_f(a3);
            c = fmaf(fg, c, ig * gg);
            float hn = og * tanh_f(c);
            hx[((s + 1) & 1) * 256 + b_l * 32 + u_l] = hn;   // own exchange slice
            out[(size_t)(gb + b_l) * (TT * UU) + (size_t)s * UU + gcol] = hn;
            if (s == TT - 1 && write_hc) {
                out[(size_t)BB * TT * UU + (size_t)(gb + b_l) * UU + gcol] = hn;
                out[(size_t)BB * TT * UU + (size_t)BB * UU + (size_t)(gb + b_l) * UU + gcol] = c;
            }
        }

        // -------- cluster HW barrier: release own slice, acquire peers' --------
        if (s + 1 < TT) {
            asm volatile("barrier.cluster.arrive.aligned;" ::: "memory");
            asm volatile("barrier.cluster.wait.aligned;"   ::: "memory");
        }
    }

    // no CTA may exit while peers could still read its SMEM
    asm volatile("barrier.cluster.arrive.aligned;" ::: "memory");
    asm volatile("barrier.cluster.wait.aligned;"   ::: "memory");
}

extern "C" void kernel_launch(void* const* d_in, const int* in_sizes, int n_in,
                              void* d_out, int out_size) {
    const float* x    = (const float*)d_in[0];
    const float* Wx   = (const float*)d_in[1];
    const float* Wh   = (const float*)d_in[2];
    const float* bias = (const float*)d_in[3];
    float* out = (float*)d_out;

    long long need = (long long)BB * TT * UU + 2LL * BB * UU;
    int write_hc = ((long long)out_size >= need) ? 1 : 0;

    cudaFuncSetAttribute(lstm_persistent_kernel,
                         cudaFuncAttributeMaxDynamicSharedMemorySize, SMEM_BYTES);

    lstm_persistent_kernel<<<NCTA, NTHR, SMEM_BYTES>>>(x, Wx, Wh, bias, out, write_hc);
}

// round 9
// speedup vs baseline: 1.5275x; 1.5275x over previous
#include <cuda_runtime.h>
#include <cstdint>

// LSTM B=128, T=2048, F=3, U=256. 16 clusters x 8 CTAs, CTA = 8 batch rows x 32 units (128 gate cols).
// R5: k-pair FFMA2 GEMM (Wh k-interleaved, h operand = natural {h_2k,h_2k+1} pairs, no duplication,
//     ~2800 L1 wavefronts/step). h exchange: 8x cp.async.bulk (1152B) -> every rank's recv buffer,
//     mbarrier complete_tx; consumer does ONE parity wait then reads recv directly in the GEMM.
//     No barrier.cluster / atomics / spins in the loop.

#define BB 128
#define TT 2048
#define FF 3
#define UU 256
#define G4 1024
#define NCTA 128
#define NTHR 256
#define CLUSTER 8

// SMEM layout (float offsets)
#define OFF_WH2  0        // 128 kp * 128 cols * 2 = 32768 : wh2[kp][col] = {w_2kp,c , w_2kp+1,c}
#define OFF_RECV 32768    // 2 bufs * 8 ranks * 288 = 4608 : rank block = [b=8][36] (32 data + 4 pad)
#define OFF_HX   37376    // 2 bufs * 288 = 576 : own h slice staging [b][36]
#define OFF_BIAS 37952    // 128  (permuted)
#define OFF_WX   38080    // 384  (permuted)
#define OFF_XS   38464    // 2*8 = 16 (x tile per parity: 8 slots, 6 used)
#define OFF_MBAR 38480    // 2 mbarriers (16B)
#define SMEM_FLOATS 38484
#define SMEM_BYTES (SMEM_FLOATS * 4)

#define BLK_FLOATS 288          // one rank block: 8*36
#define BLK_BYTES  1152
#define BUF_BYTES  (8 * BLK_BYTES)   // 9216 per recv parity buffer
#define TX_BYTES   BUF_BYTES

__device__ __forceinline__ float sig_f(float x) {
    x = fminf(fmaxf(x, -30.f), 30.f);
    float e = __expf(-x);
    return __fdividef(1.f, 1.f + e);
}

__device__ __forceinline__ float tanh_f(float x) {
    float ax = fminf(fabsf(x), 15.f);
    float e = __expf(-2.f * ax);
    float r = __fdividef(1.f - e, 1.f + e);
    return copysignf(r, x);
}

__device__ __forceinline__ void ffma2(unsigned long long& acc,
                                      unsigned long long a,
                                      unsigned long long b) {
    asm("fma.rn.f32x2 %0, %1, %2, %0;" : "+l"(acc) : "l"(a), "l"(b));
}

__device__ __forceinline__ void mbar_init(uint32_t addr, uint32_t cnt) {
    asm volatile("mbarrier.init.shared.b64 [%0], %1;" :: "r"(addr), "r"(cnt) : "memory");
}
__device__ __forceinline__ void mbar_arrive_expect_tx(uint32_t addr, uint32_t tx) {
    asm volatile("mbarrier.arrive.expect_tx.shared.b64 _, [%0], %1;"
                 :: "r"(addr), "r"(tx) : "memory");
}
__device__ __forceinline__ void mbar_wait(uint32_t addr, uint32_t parity) {
    uint32_t done;
    asm volatile(
        "{\n\t.reg .pred p;\n\t"
        "mbarrier.try_wait.parity.acquire.cta.shared::cta.b64 p, [%1], %2;\n\t"
        "selp.b32 %0, 1, 0, p;\n\t}"
        : "=r"(done) : "r"(addr), "r"(parity) : "memory");
    if (!done) {
        asm volatile(
            "{\n\t.reg .pred P1;\n\t"
            "WAIT_LOOP_%=:\n\t"
            "mbarrier.try_wait.parity.acquire.cta.shared::cta.b64 P1, [%0], %1, 0x989680;\n\t"
            "@P1 bra.uni WAIT_DONE_%=;\n\t"
            "bra.uni WAIT_LOOP_%=;\n\t"
            "WAIT_DONE_%=:\n\t}"
            :: "r"(addr), "r"(parity) : "memory");
    }
}
__device__ __forceinline__ void bulk_copy_s2c(uint32_t dst_cluster, uint32_t src_cta,
                                              uint32_t bytes, uint32_t mbar_cluster) {
    asm volatile(
        "cp.async.bulk.shared::cluster.shared::cta.mbarrier::complete_tx::bytes "
        "[%0], [%1], %2, [%3];"
        :: "r"(dst_cluster), "r"(src_cta), "r"(bytes), "r"(mbar_cluster) : "memory");
}

__global__ void __launch_bounds__(NTHR, 1) __cluster_dims__(CLUSTER, 1, 1)
lstm_persistent_kernel(
    const float* __restrict__ x,     // [B, T, F]
    const float* __restrict__ Wx,    // [F, 4U]
    const float* __restrict__ Wh,    // [U, 4U]
    const float* __restrict__ bias,  // [4U]
    float* __restrict__ out,         // ys [B,T,U] (+ h_T, c_T if write_hc)
    int write_hc)
{
    extern __shared__ float sm[];
    float* wh2 = sm + OFF_WH2;
    float* bs  = sm + OFF_BIAS;
    float* wxs = sm + OFF_WX;
    float* xs  = sm + OFF_XS;
    float* hx  = sm + OFF_HX;

    const int tid = threadIdx.x;
    const int RB  = blockIdx.x >> 3;   // cluster id 0..15
    const int CB  = blockIdx.x & 7;    // rank in cluster = gate-column block
    const int gb  = RB * 8;

    const uint32_t smem_u32 = (uint32_t)__cvta_generic_to_shared(sm);
    const uint32_t mbarL = smem_u32 + OFF_MBAR * 4;   // [0]: even steps, [8]: odd steps

    // per-rank DSMEM base addresses
    uint32_t r_base[CLUSTER];
    #pragma unroll
    for (int r = 0; r < CLUSTER; r++)
        asm("mapa.shared::cluster.u32 %0, %1, %2;"
            : "=r"(r_base[r]) : "r"(smem_u32), "r"(r));

    // ---------------- setup ----------------
    // wh2[kp*256 + col*2 + {0,1}] = Wh[(2kp)|(2kp+1)][g*256 + CB*32 + u], col = u*4+g
    for (int i = tid; i < 128 * 128; i += NTHR) {
        int kp = i >> 7, col = i & 127;
        int u = col >> 2, g = col & 3;
        int gc = g * UU + CB * 32 + u;
        wh2[kp * 256 + col * 2 + 0] = Wh[(2 * kp)     * G4 + gc];
        wh2[kp * 256 + col * 2 + 1] = Wh[(2 * kp + 1) * G4 + gc];
    }
    #pragma unroll
    for (int g = 0; g < 4; g++) {
        const int gbase = g * UU + CB * 32;
        for (int i = tid; i < 3 * 32; i += NTHR) {
            int f = i >> 5, ul = i & 31;
            wxs[f * 128 + ul * 4 + g] = Wx[f * G4 + gbase + ul];
        }
    }
    if (tid < 128) {
        int ul = tid >> 2, g = tid & 3;
        bs[tid] = bias[g * UU + CB * 32 + ul];
    }
    // zero recv buffers (step 0 reads buf0 as h=0) and hx pads
    for (int i = tid; i < 2 * 8 * BLK_FLOATS; i += NTHR) sm[OFF_RECV + i] = 0.f;
    for (int i = tid; i < 2 * BLK_FLOATS; i += NTHR)     sm[OFF_HX + i]   = 0.f;

    const int u_l = tid >> 3;   // 0..31
    const int b_l = tid & 7;    // 0..7
    const int gcol = CB * 32 + u_l;

    // x[t=0] into xs[parity 0]
    if (tid < 24) xs[tid] = __ldg(&x[(size_t)(gb + tid / 3) * (TT * FF) + tid % 3]);

    // arm both mbarriers before any peer can send (cluster sync below orders this)
    if (tid == 0) {
        mbar_init(mbarL, 1);
        mbar_init(mbarL + 8, 1);
        mbar_arrive_expect_tx(mbarL, TX_BYTES);
        mbar_arrive_expect_tx(mbarL + 8, TX_BYTES);
    }

    float c = 0.f;

    __syncthreads();
    asm volatile("barrier.cluster.arrive.aligned;" ::: "memory");
    asm volatile("barrier.cluster.wait.aligned;"   ::: "memory");

    int ph0 = 0, ph1 = 0;

    // GEMM base pointers
    const float* whp = wh2 + u_l * 8;                 // col*2 with col=u_l*4 -> u_l*8

    for (int s = 0; s < TT; s++) {
        const int p = s & 1;

        // -------- wait for this step's h (recv buffer p), re-arm for s+2 --------
        if (s > 0) {
            if (p) { mbar_wait(mbarL + 8, ph1); ph1 ^= 1; }
            else   { mbar_wait(mbarL,     ph0); ph0 ^= 1; }
            if (tid == 0) mbar_arrive_expect_tx(mbarL + (p ? 8 : 0), TX_BYTES);
        }

        // prefetch next x early (lands during GEMM)
        float xpre = 0.f;
        if (tid < 24 && s + 1 < TT)
            xpre = __ldg(&x[(size_t)(gb + tid / 3) * (TT * FF) + (size_t)(s + 1) * FF + tid % 3]);

        // -------- acc init: bias + x @ Wx (scalar), pack into {even,odd} accs --------
        float i0, i1, i2, i3;
        {
            float4 bb4 = *reinterpret_cast<const float4*>(bs + u_l * 4);
            i0 = bb4.x; i1 = bb4.y; i2 = bb4.z; i3 = bb4.w;
            float xv0 = xs[p * 8 + b_l * 3 + 0] * 0.f + xs[p * 8 + 0 * 0];  // placeholder avoided below
            (void)xv0;
        }
        {
            float xv0 = xs[p * 8 + b_l];           // unused pattern guard
            (void)xv0;
        }
        // (real init, xs layout: [p][b*3+f] packed in 8 slots is too small -> use 2*16)
        // NOTE: xs region holds 16 floats; we use [p*8 + 0..5]? Not enough for 8 rows * 3.
        // Corrected below: xs actually indexed [p][b_l*3+f] requires 24 slots; we use OFF_XS..+
        // -> handled by the wider indexing into sm[] directly:
        {
            const float* xsp = sm + OFF_XS;  // reinterpret: we allocated 16 floats; need 48.
            (void)xsp;
        }

        // ---- proper init using direct x values staged in hx pad area is avoided;
        //      we instead recompute from xq registers below ----
        float xq0, xq1, xq2;
        {
            // x values for my batch row, staged per-step in shared (region after xs misuse fix):
            const float* xrow = sm + OFF_XS + p * 24;   // see storage below (48 floats total)
            xq0 = xrow[b_l * 3 + 0];
            xq1 = xrow[b_l * 3 + 1];
            xq2 = xrow[b_l * 3 + 2];
        }
        {
            float4 w;
            w = *reinterpret_cast<const float4*>(wxs + 0 * 128 + u_l * 4);
            i0 = fmaf(xq0, w.x, i0); i1 = fmaf(xq0, w.y, i1);
            i2 = fmaf(xq0, w.z, i2); i3 = fmaf(xq0, w.w, i3);
            w = *reinterpret_cast<const float4*>(wxs + 1 * 128 + u_l * 4);
            i0 = fmaf(xq1, w.x, i0); i1 = fmaf(xq1, w.y, i1);
            i2 = fmaf(xq1, w.z, i2); i3 = fmaf(xq1, w.w, i3);
            w = *reinterpret_cast<const float4*>(wxs + 2 * 128 + u_l * 4);
            i0 = fmaf(xq2, w.x, i0); i1 = fmaf(xq2, w.y, i1);
            i2 = fmaf(xq2, w.z, i2); i3 = fmaf(xq2, w.w, i3);
        }

        unsigned long long a0, a1, a2, a3;
        {
            float z = 0.f;
            asm("mov.b64 %0, {%1, %2};" : "=l"(a0) : "f"(i0), "f"(z));
            asm("mov.b64 %0, {%1, %2};" : "=l"(a1) : "f"(i1), "f"(z));
            asm("mov.b64 %0, {%1, %2};" : "=l"(a2) : "f"(i2), "f"(z));
            asm("mov.b64 %0, {%1, %2};" : "=l"(a3) : "f"(i3), "f"(z));
        }

        // -------- GEMM: k-pair FFMA2, K=256 (128 pairs), h read straight from recv --------
        {
            const float* rbuf = sm + OFF_RECV + p * (8 * BLK_FLOATS) + b_l * 36;
            const float* whk = whp;
            #pragma unroll 8
            for (int kp2 = 0; kp2 < 64; kp2++) {
                // h for k = 4*kp2 .. 4*kp2+3 : rank r = kp2>>3, within-block word (kp2&7)*4
                int r  = kp2 >> 3;
                int ko = (kp2 & 7) * 4;
                ulonglong2 hv2 = *reinterpret_cast<const ulonglong2*>(rbuf + r * BLK_FLOATS + ko);
                // kp = 2*kp2 : cols {0,1} then {2,3}
                ulonglong2 w01a = *reinterpret_cast<const ulonglong2*>(whk);
                ulonglong2 w23a = *reinterpret_cast<const ulonglong2*>(whk + 4);
                ffma2(a0, hv2.x, w01a.x);
                ffma2(a1, hv2.x, w01a.y);
                ffma2(a2, hv2.x, w23a.x);
                ffma2(a3, hv2.x, w23a.y);
                ulonglong2 w01b = *reinterpret_cast<const ulonglong2*>(whk + 256);
                ulonglong2 w23b = *reinterpret_cast<const ulonglong2*>(whk + 260);
                ffma2(a0, hv2.y, w01b.x);
                ffma2(a1, hv2.y, w01b.y);
                ffma2(a2, hv2.y, w23b.x);
                ffma2(a3, hv2.y, w23b.y);
                whk += 512;
            }
        }

        float z0, z1, z2, z3;
        {
            float lo, hi;
            asm("mov.b64 {%0, %1}, %2;" : "=f"(lo), "=f"(hi) : "l"(a0)); z0 = lo + hi;
            asm("mov.b64 {%0, %1}, %2;" : "=f"(lo), "=f"(hi) : "l"(a1)); z1 = lo + hi;
            asm("mov.b64 {%0, %1}, %2;" : "=f"(lo), "=f"(hi) : "l"(a2)); z2 = lo + hi;
            asm("mov.b64 {%0, %1}, %2;" : "=f"(lo), "=f"(hi) : "l"(a3)); z3 = lo + hi;
        }

        // -------- gates / state --------
        float ig = sig_f(z0);
        float fg = sig_f(z1);
        float gg = tanh_f(z2);
        float og = sig_f(z3);
        c = fmaf(fg, c, ig * gg);
        float hn = og * tanh_f(c);

        // -------- stage own slice + next x, then bulk-send to all ranks --------
        const int pn = (s + 1) & 1;
        if (s + 1 < TT) {
            hx[pn * BLK_FLOATS + b_l * 36 + u_l] = hn;
            if (tid < 24) sm[OFF_XS + pn * 24 + tid] = xpre;
            __syncthreads();
            if (tid == 0) {
                asm volatile("fence.proxy.async.shared::cta;" ::: "memory");
                const uint32_t src = smem_u32 + (uint32_t)(OFF_HX + pn * BLK_FLOATS) * 4;
                const uint32_t doff = (uint32_t)OFF_RECV * 4 + (uint32_t)pn * BUF_BYTES
                                      + (uint32_t)CB * BLK_BYTES;
                const uint32_t moff = (uint32_t)OFF_MBAR * 4 + (uint32_t)pn * 8;
                #pragma unroll
                for (int r = 0; r < CLUSTER; r++)
                    bulk_copy_s2c(r_base[r] + doff, src, BLK_BYTES, r_base[r] + moff);
            }
        }

        // -------- outputs (off critical path) --------
        out[(size_t)(gb + b_l) * (TT * UU) + (size_t)s * UU + gcol] = hn;
        if (s == TT - 1 && write_hc) {
            out[(size_t)BB * TT * UU + (size_t)(gb + b_l) * UU + gcol] = hn;
            out[(size_t)BB * TT * UU + (size_t)BB * UU + (size_t)(gb + b_l) * UU + gcol] = c;
        }
    }

    asm volatile("barrier.cluster.arrive.aligned;" ::: "memory");
    asm volatile("barrier.cluster.wait.aligned;"   ::: "memory");
}

extern "C" void kernel_launch(void* const* d_in, const int* in_sizes, int n_in,
                              void* d_out, int out_size) {
    const float* x    = (const float*)d_in[0];
    const float* Wx   = (const float*)d_in[1];
    const float* Wh   = (const float*)d_in[2];
    const float* bias = (const float*)d_in[3];
    float* out = (float*)d_out;

    long long need = (long long)BB * TT * UU + 2LL * BB * UU;
    int write_hc = ((long long)out_size >= need) ? 1 : 0;

    cudaFuncSetAttribute(lstm_persistent_kernel,
                         cudaFuncAttributeMaxDynamicSharedMemorySize, SMEM_BYTES + 64 * 4);

    lstm_persistent_kernel<<<NCTA, NTHR, SMEM_BYTES + 64 * 4>>>(x, Wx, Wh, bias, out, write_hc);
}